// round 1
// baseline (speedup 1.0000x reference)
#include <cuda_runtime.h>

// Correlation layer: out[n, q, y, x] = (1/256) * sum_c d1[n,c,y,x] * d2[n,c,y+dy,x+dx]
// q = (dy+4)*9 + (dx+4), dy,dx in [-4,4], zero padding outside HxW.
// N=8, C=256, H=96, W=160, out channels 81.

#define HH 96
#define WW 160
#define CC 256
#define NN 8
#define TX 32   // tile width (x)
#define TY 8    // tile height (y)
#define CK 8    // channel chunk
#define NTHREADS 576  // (TX/4)=8 x-quads * 9 dy * TY=8 rows

__global__ __launch_bounds__(NTHREADS, 1)
void corr_kernel(const float* __restrict__ d1,
                 const float* __restrict__ d2,
                 float* __restrict__ out)
{
    __shared__ float s1[CK][TY][TX];          // 8*8*32*4   = 8 KB
    __shared__ float s2[CK][TY + 8][TX + 8];  // 8*16*40*4  = 20 KB

    const int tid = threadIdx.x;
    const int qx  = tid & 7;          // x-quad index 0..7
    const int dyi = (tid >> 3) % 9;   // dy index 0..8  (dy = dyi-4)
    const int ty  = tid / 72;         // row in tile 0..7

    const int x0 = blockIdx.x * TX;
    const int y0 = blockIdx.y * TY;
    const int n  = blockIdx.z;

    const float* __restrict__ p1 = d1 + (size_t)n * CC * HH * WW;
    const float* __restrict__ p2 = d2 + (size_t)n * CC * HH * WW;

    float acc[9][4];
    #pragma unroll
    for (int i = 0; i < 9; i++)
        #pragma unroll
        for (int j = 0; j < 4; j++)
            acc[i][j] = 0.0f;

    for (int c0 = 0; c0 < CC; c0 += CK) {
        __syncthreads();  // protect smem from previous iteration's readers

        // ---- load s1: CK*TY*TX = 2048 floats = 512 float4, threads 0..511 ----
        if (tid < 512) {
            const int c    = tid >> 6;        // /64  (64 float4 per channel)
            const int rem  = tid & 63;
            const int row  = rem >> 3;        // /8
            const int col4 = rem & 7;
            const float4 v = reinterpret_cast<const float4*>(
                p1 + (size_t)(c0 + c) * (HH * WW) + (y0 + row) * WW + x0)[col4];
            reinterpret_cast<float4*>(&s1[c][row][0])[col4] = v;
        }

        // ---- load s2 with halo: CK*(TY+8)*(TX+8) = 5120 scalars ----
        #pragma unroll
        for (int i = 0; i < 9; i++) {
            const int idx = tid + i * NTHREADS;
            if (idx < CK * (TY + 8) * (TX + 8)) {
                const int c   = idx / 640;            // (TY+8)*(TX+8)=640
                const int rem = idx - c * 640;
                const int row = rem / 40;
                const int col = rem - row * 40;
                const int gy  = y0 + row - 4;
                const int gx  = x0 + col - 4;
                float v = 0.0f;
                if ((unsigned)gy < (unsigned)HH && (unsigned)gx < (unsigned)WW)
                    v = p2[(size_t)(c0 + c) * (HH * WW) + gy * WW + gx];
                s2[c][row][col] = v;
            }
        }

        __syncthreads();

        // ---- compute: per channel, 4 pixels x 9 dx FMAs for this thread's dy ----
        #pragma unroll
        for (int c = 0; c < CK; c++) {
            const float4 a = *reinterpret_cast<const float4*>(&s1[c][ty][qx * 4]);
            const float4* wp = reinterpret_cast<const float4*>(&s2[c][ty + dyi][qx * 4]);
            const float4 w0 = wp[0];
            const float4 w1 = wp[1];
            const float4 w2 = wp[2];
            float w[12];
            w[0]=w0.x; w[1]=w0.y; w[2]=w0.z; w[3]=w0.w;
            w[4]=w1.x; w[5]=w1.y; w[6]=w1.z; w[7]=w1.w;
            w[8]=w2.x; w[9]=w2.y; w[10]=w2.z; w[11]=w2.w;

            #pragma unroll
            for (int dxi = 0; dxi < 9; dxi++) {
                acc[dxi][0] = fmaf(a.x, w[dxi + 0], acc[dxi][0]);
                acc[dxi][1] = fmaf(a.y, w[dxi + 1], acc[dxi][1]);
                acc[dxi][2] = fmaf(a.z, w[dxi + 2], acc[dxi][2]);
                acc[dxi][3] = fmaf(a.w, w[dxi + 3], acc[dxi][3]);
            }
        }
    }

    // ---- write out: 9 float4 stores (one per dx) ----
    const float scale = 1.0f / 256.0f;
    const int y  = y0 + ty;
    const int xb = x0 + qx * 4;
    #pragma unroll
    for (int dxi = 0; dxi < 9; dxi++) {
        const int q = dyi * 9 + dxi;
        float4 o;
        o.x = acc[dxi][0] * scale;
        o.y = acc[dxi][1] * scale;
        o.z = acc[dxi][2] * scale;
        o.w = acc[dxi][3] * scale;
        *reinterpret_cast<float4*>(
            out + (((size_t)n * 81 + q) * HH + y) * WW + xb) = o;
    }
}

extern "C" void kernel_launch(void* const* d_in, const int* in_sizes, int n_in,
                              void* d_out, int out_size)
{
    const float* d1 = (const float*)d_in[0];
    const float* d2 = (const float*)d_in[1];
    float* out = (float*)d_out;

    dim3 grid(WW / TX, HH / TY, NN);   // (5, 12, 8)
    corr_kernel<<<grid, NTHREADS>>>(d1, d2, out);
}

// round 2
// speedup vs baseline: 1.7504x; 1.7504x over previous
#include <cuda_runtime.h>
#include <cstdint>

// Correlation: out[n,q,y,x] = (1/256) * sum_c d1[n,c,y,x] * d2[n,c,y+dy,x+dx]
// q = (dy+4)*9 + (dx+4), zero padding. N=8, C=256, H=96, W=160, 81 out channels.

#define HH 96
#define WW 160
#define CC 256
#define NN 8
#define TX 32
#define TY 8
#define CK 8
#define NTHREADS 576               // 8 x-quads * 9 dy * 8 rows
#define S1_ELEMS (CK*TY*TX)        // 2048 floats
#define S2_ROWS  (TY+8)            // 16
#define S2_COLS  (TX+8)            // 40
#define S2_ELEMS (CK*S2_ROWS*S2_COLS)  // 5120 floats
#define BUF_ELEMS (S1_ELEMS + S2_ELEMS)  // 7168 floats per stage
#define SMEM_BYTES (2 * BUF_ELEMS * 4)   // 57344

__device__ __forceinline__ void cp_async16(uint32_t dst, const float* src) {
    asm volatile("cp.async.cg.shared.global [%0], [%1], 16;\n" :: "r"(dst), "l"(src));
}
__device__ __forceinline__ void cp_commit() {
    asm volatile("cp.async.commit_group;\n" ::: "memory");
}
__device__ __forceinline__ void cp_wait0() {
    asm volatile("cp.async.wait_group 0;\n" ::: "memory");
}

__global__ __launch_bounds__(NTHREADS, 1)
void corr_kernel(const float* __restrict__ d1,
                 const float* __restrict__ d2,
                 float* __restrict__ out)
{
    extern __shared__ float smem[];
    // stage b: s1 at b*BUF_ELEMS, s2 at b*BUF_ELEMS + S1_ELEMS
    const int tid = threadIdx.x;
    const int qx  = tid & 7;
    const int dyi = (tid >> 3) % 9;
    const int ty  = tid / 72;

    const int x0 = blockIdx.x * TX;
    const int y0 = blockIdx.y * TY;
    const int n  = blockIdx.z;

    const float* __restrict__ p1 = d1 + (size_t)n * CC * HH * WW;
    const float* __restrict__ p2 = d2 + (size_t)n * CC * HH * WW;

    const uint32_t smem_u32 = (uint32_t)__cvta_generic_to_shared(smem);

    // ---- zero both s2 buffers once (OOB halo cells stay zero forever) ----
    {
        float4 z = make_float4(0.f, 0.f, 0.f, 0.f);
        #pragma unroll
        for (int b = 0; b < 2; b++) {
            float4* s2v = reinterpret_cast<float4*>(smem + b * BUF_ELEMS + S1_ELEMS);
            for (int i = tid; i < S2_ELEMS / 4; i += NTHREADS) s2v[i] = z;
        }
    }

    // ---- precompute per-thread load tasks (coords fixed; only c0*HW varies) ----
    // s1: one float4 task for tid < 512
    const int  t1_c    = tid >> 6;
    const int  t1_rem  = tid & 63;
    const int  t1_row  = t1_rem >> 3;
    const int  t1_col4 = t1_rem & 7;
    const bool t1_valid = (tid < 512);
    const size_t t1_src = (size_t)t1_c * (HH * WW) + (size_t)(y0 + t1_row) * WW + x0 + t1_col4 * 4;
    const uint32_t t1_dst = ((t1_c * TY + t1_row) * TX + t1_col4 * 4) * 4;

    // s2: up to 3 float4 tasks per thread (1280 tasks total)
    bool     t2_valid[3];
    size_t   t2_src[3];
    uint32_t t2_dst[3];
    #pragma unroll
    for (int i = 0; i < 3; i++) {
        const int idx = tid + i * NTHREADS;
        bool v = (idx < CK * S2_ROWS * 10);
        int c = 0, row = 0, grp = 0;
        if (v) {
            c   = idx / (S2_ROWS * 10);
            int rem = idx - c * (S2_ROWS * 10);
            row = rem / 10;
            grp = rem - row * 10;
        }
        const int gy  = y0 + row - 4;
        const int gx0 = x0 + grp * 4 - 4;
        v = v && ((unsigned)gy < (unsigned)HH) && (gx0 >= 0) && (gx0 + 3 < WW);
        t2_valid[i] = v;
        t2_src[i]   = (size_t)c * (HH * WW) + (size_t)(gy < 0 ? 0 : gy) * WW + (gx0 < 0 ? 0 : gx0);
        t2_dst[i]   = (S1_ELEMS + (c * S2_ROWS + row) * S2_COLS + grp * 4) * 4;
    }

    float acc[9][4];
    #pragma unroll
    for (int i = 0; i < 9; i++)
        #pragma unroll
        for (int j = 0; j < 4; j++) acc[i][j] = 0.0f;

    // ---- prologue: issue chunk 0 into stage 0 ----
    {
        if (t1_valid) cp_async16(smem_u32 + t1_dst, p1 + t1_src);
        #pragma unroll
        for (int i = 0; i < 3; i++)
            if (t2_valid[i]) cp_async16(smem_u32 + t2_dst[i], p2 + t2_src[i]);
        cp_commit();
    }

    const int NCHUNK = CC / CK;  // 32
    #pragma unroll 1
    for (int ci = 0; ci < NCHUNK; ci++) {
        cp_wait0();
        __syncthreads();   // chunk ci data visible; all threads done computing ci-1

        // issue loads for chunk ci+1 into the other stage (overlapped with compute)
        if (ci + 1 < NCHUNK) {
            const size_t coff = (size_t)(ci + 1) * CK * (HH * WW);
            const uint32_t sb = smem_u32 + ((ci + 1) & 1) * (BUF_ELEMS * 4);
            if (t1_valid) cp_async16(sb + t1_dst, p1 + coff + t1_src);
            #pragma unroll
            for (int i = 0; i < 3; i++)
                if (t2_valid[i]) cp_async16(sb + t2_dst[i], p2 + coff + t2_src[i]);
        }
        cp_commit();  // commit (possibly empty) group so wait_group count stays aligned

        // ---- compute chunk ci ----
        const float* __restrict__ s1 = smem + (ci & 1) * BUF_ELEMS;
        const float* __restrict__ s2 = s1 + S1_ELEMS;

        #pragma unroll
        for (int c = 0; c < CK; c++) {
            const float4 a = *reinterpret_cast<const float4*>(
                s1 + (c * TY + ty) * TX + qx * 4);
            const float4* wp = reinterpret_cast<const float4*>(
                s2 + (c * S2_ROWS + ty + dyi) * S2_COLS + qx * 4);
            const float4 w0 = wp[0];
            const float4 w1 = wp[1];
            const float4 w2 = wp[2];
            float w[12];
            w[0]=w0.x; w[1]=w0.y; w[2]=w0.z;  w[3]=w0.w;
            w[4]=w1.x; w[5]=w1.y; w[6]=w1.z;  w[7]=w1.w;
            w[8]=w2.x; w[9]=w2.y; w[10]=w2.z; w[11]=w2.w;

            #pragma unroll
            for (int dxi = 0; dxi < 9; dxi++) {
                acc[dxi][0] = fmaf(a.x, w[dxi + 0], acc[dxi][0]);
                acc[dxi][1] = fmaf(a.y, w[dxi + 1], acc[dxi][1]);
                acc[dxi][2] = fmaf(a.z, w[dxi + 2], acc[dxi][2]);
                acc[dxi][3] = fmaf(a.w, w[dxi + 3], acc[dxi][3]);
            }
        }
    }

    // ---- epilogue: 9 float4 stores per thread ----
    const float scale = 1.0f / 256.0f;
    const int y  = y0 + ty;
    const int xb = x0 + qx * 4;
    #pragma unroll
    for (int dxi = 0; dxi < 9; dxi++) {
        const int q = dyi * 9 + dxi;
        float4 o;
        o.x = acc[dxi][0] * scale;
        o.y = acc[dxi][1] * scale;
        o.z = acc[dxi][2] * scale;
        o.w = acc[dxi][3] * scale;
        *reinterpret_cast<float4*>(
            out + (((size_t)n * 81 + q) * HH + y) * WW + xb) = o;
    }
}

extern "C" void kernel_launch(void* const* d_in, const int* in_sizes, int n_in,
                              void* d_out, int out_size)
{
    const float* d1 = (const float*)d_in[0];
    const float* d2 = (const float*)d_in[1];
    float* out = (float*)d_out;

    cudaFuncSetAttribute(corr_kernel,
                         cudaFuncAttributeMaxDynamicSharedMemorySize, SMEM_BYTES);

    dim3 grid(WW / TX, HH / TY, NN);   // (5, 12, 8)
    corr_kernel<<<grid, NTHREADS, SMEM_BYTES>>>(d1, d2, out);
}